// round 16
// baseline (speedup 1.0000x reference)
#include <cuda_runtime.h>
#include <cuda_fp16.h>
#include <cstdint>
#include <cstddef>

// ---------------- problem constants ----------------
#define B_   8
#define T_   12
#define P_   1000
#define N_   20000
#define E_   60000
#define FP_  32
#define FN_  32
#define H_   12
#define KD_  384                 // GEMM1 K after PW split
#define HID_ 768
#define M_   (B_ * N_)           // 160000 rows
#define BP_  (B_ * P_)           // 8000 distinct patch rows
#define SLOTS_ 32                // padded fan-in per node (max observed ~15)

// ---------------- device scratch ----------------
__device__ __half g_X[(size_t)M_ * KD_];
__device__ __half g_W1t[HID_ * KD_];        // W1 top half transposed
__device__ __half g_W1bt[HID_ * KD_];       // W1 bottom half transposed
__device__ __half g_Pf[BP_ * KD_];
__device__ __half g_PW[(size_t)BP_ * HID_];
__device__ __half g_MX[(size_t)M_ * HID_];  // per-row mean of PW rows
__device__ int    g_cnt[N_];                // per-node edge count (zeroed by k_conv)
__device__ int    g_eslot[N_ * SLOTS_];     // padded per-node patch indices

// ---------------- fused conversions + cnt zeroing ----------------
#define W1T_WORK (HID_ * HID_)
#define NX_WORK  (B_ * T_ * N_ * 4)
#define PF_WORK  (B_ * T_ * P_ * 4)
#define CONV_WORK (W1T_WORK + NX_WORK + PF_WORK + N_)
__global__ void k_conv(const float* __restrict__ W1, const float* __restrict__ nodes_x,
                       const float* __restrict__ patch) {
    int i = blockIdx.x * blockDim.x + threadIdx.x;
    if (i < W1T_WORK) {
        int k = i / HID_, h = i % HID_;
        __half v = __float2half_rn(W1[i]);
        if (k < KD_) g_W1t[h * KD_ + k] = v;
        else         g_W1bt[h * KD_ + (k - KD_)] = v;
    } else if (i < W1T_WORK + NX_WORK) {
        int j = i - W1T_WORK;
        int q  = j & 3;
        int n  = (j >> 2) % N_;
        int bt = (j >> 2) / N_;
        int b = bt / T_, t = bt % T_;
        const float4* src = (const float4*)(nodes_x + ((size_t)bt * N_ + n) * FN_ + q * 8);
        float4 a = src[0], c = src[1];
        union { __half2 h[4]; uint4 u; } cv;
        cv.h[0] = __floats2half2_rn(a.x, a.y);
        cv.h[1] = __floats2half2_rn(a.z, a.w);
        cv.h[2] = __floats2half2_rn(c.x, c.y);
        cv.h[3] = __floats2half2_rn(c.z, c.w);
        *(uint4*)&g_X[((size_t)(b * N_ + n)) * KD_ + t * FN_ + q * 8] = cv.u;
    } else if (i < W1T_WORK + NX_WORK + PF_WORK) {
        int j = i - W1T_WORK - NX_WORK;
        int q  = j & 3;
        int p  = (j >> 2) % P_;
        int bt = (j >> 2) / P_;
        int b = bt / T_, t = bt % T_;
        const float4* src = (const float4*)(patch + ((size_t)bt * P_ + p) * FP_ + q * 8);
        float4 a = src[0], c = src[1];
        union { __half2 h[4]; uint4 u; } cv;
        cv.h[0] = __floats2half2_rn(a.x, a.y);
        cv.h[1] = __floats2half2_rn(a.z, a.w);
        cv.h[2] = __floats2half2_rn(c.x, c.y);
        cv.h[3] = __floats2half2_rn(c.z, c.w);
        *(uint4*)&g_Pf[((size_t)(b * P_ + p)) * KD_ + t * FP_ + q * 8] = cv.u;
    } else if (i < CONV_WORK) {
        g_cnt[i - (W1T_WORK + NX_WORK + PF_WORK)] = 0;
    }
}

// ---------------- edge scatter into padded slots ----------------
__global__ void k_scatter(const int* __restrict__ mapper, const int* __restrict__ batch) {
    int e = blockIdx.x * blockDim.x + threadIdx.x;
    if (e < E_) {
        int n = mapper[e];
        int idx = atomicAdd(&g_cnt[n], 1);
        if (idx < SLOTS_) g_eslot[n * SLOTS_ + idx] = batch[e];
    }
}

// ---------------- mma helpers ----------------
__device__ __forceinline__ uint32_t smem_u32(const void* p) {
    uint32_t a;
    asm volatile("{ .reg .u64 t; cvta.to.shared.u64 t, %1; cvt.u32.u64 %0, t; }"
                 : "=r"(a) : "l"(p));
    return a;
}
__device__ __forceinline__ void ldsm4(uint32_t* r, uint32_t addr) {
    asm volatile("ldmatrix.sync.aligned.m8n8.x4.shared.b16 {%0,%1,%2,%3}, [%4];"
                 : "=r"(r[0]), "=r"(r[1]), "=r"(r[2]), "=r"(r[3]) : "r"(addr));
}
__device__ __forceinline__ void mma16816(float* c, const uint32_t* a,
                                         uint32_t b0, uint32_t b1) {
    asm volatile("mma.sync.aligned.m16n8k16.row.col.f32.f16.f16.f32 "
                 "{%0,%1,%2,%3}, {%4,%5,%6,%7}, {%8,%9}, {%0,%1,%2,%3};"
                 : "+f"(c[0]), "+f"(c[1]), "+f"(c[2]), "+f"(c[3])
                 : "r"(a[0]), "r"(a[1]), "r"(a[2]), "r"(a[3]), "r"(b0), "r"(b1));
}
__device__ __forceinline__ uint32_t packh2(float a, float b) {
    __half2 h = __floats2half2_rn(a, b);
    return *(uint32_t*)&h;
}
#define CPASYNC16(dst, src) \
    asm volatile("cp.async.cg.shared.global [%0], [%1], 16;" :: "r"(dst), "l"(src))
#define CPCOMMIT() asm volatile("cp.async.commit_group;" ::: "memory")
#define CPWAIT1()  asm volatile("cp.async.wait_group 1;" ::: "memory")
#define CPWAIT0()  asm volatile("cp.async.wait_group 0;" ::: "memory")

// persistent X tile: 768B pitch (48 x 16B chunks), XOR-swizzled by row
__device__ __forceinline__ uint32_t swzX(int r, int c) {
    return (uint32_t)(r * 768 + ((c ^ (r & 7)) << 4));
}

// ---------------- k_pw: PW[8000,768] = Pf @ W1bt^T ----------------
#define PW_PITCH 80
#define PW_STAGE (192 * PW_PITCH)
__global__ void __launch_bounds__(256, 1)
k_pw()
{
    __shared__ char smem[3 * PW_STAGE];
    const int tid   = threadIdx.x;
    const int lane  = tid & 31;
    const int wid   = tid >> 5;
    const int warpM = wid >> 2;
    const int warpN = wid & 3;
    const int m0    = blockIdx.x * 64;
    const int n0    = blockIdx.y * 128;
    const uint32_t tile_base = smem_u32(smem);
    const int r0 = tid >> 2;
    const int c0 = tid & 3;

    float acc[2][4][4];
#pragma unroll
    for (int mf = 0; mf < 2; ++mf)
#pragma unroll
        for (int nf = 0; nf < 4; ++nf)
#pragma unroll
            for (int q = 0; q < 4; ++q) acc[mf][nf][q] = 0.0f;

#pragma unroll
    for (int s = 0; s < 2; ++s) {
        const int k0 = s * 32;
        uint32_t sA = tile_base + s * PW_STAGE;
        uint32_t sB = sA + 64 * PW_PITCH;
        CPASYNC16(sA + r0 * PW_PITCH + c0 * 16,
                  (const void*)&g_Pf[(size_t)(m0 + r0) * KD_ + k0 + c0 * 8]);
        CPASYNC16(sB + r0 * PW_PITCH + c0 * 16,
                  (const void*)&g_W1bt[(size_t)(n0 + r0) * KD_ + k0 + c0 * 8]);
        CPASYNC16(sB + (r0 + 64) * PW_PITCH + c0 * 16,
                  (const void*)&g_W1bt[(size_t)(n0 + r0 + 64) * KD_ + k0 + c0 * 8]);
        CPCOMMIT();
    }

#pragma unroll 1
    for (int kt = 0; kt < 12; ++kt) {
        if (kt < 11) { CPWAIT1(); } else { CPWAIT0(); }
        __syncthreads();
        if (kt + 2 < 12) {
            const int k0 = (kt + 2) * 32;
            const int st = (kt + 2) % 3;
            uint32_t sA = tile_base + st * PW_STAGE;
            uint32_t sB = sA + 64 * PW_PITCH;
            CPASYNC16(sA + r0 * PW_PITCH + c0 * 16,
                      (const void*)&g_Pf[(size_t)(m0 + r0) * KD_ + k0 + c0 * 8]);
            CPASYNC16(sB + r0 * PW_PITCH + c0 * 16,
                      (const void*)&g_W1bt[(size_t)(n0 + r0) * KD_ + k0 + c0 * 8]);
            CPASYNC16(sB + (r0 + 64) * PW_PITCH + c0 * 16,
                      (const void*)&g_W1bt[(size_t)(n0 + r0 + 64) * KD_ + k0 + c0 * 8]);
            CPCOMMIT();
        }
        const int st = kt % 3;
        uint32_t sA = tile_base + st * PW_STAGE;
        uint32_t sB = sA + 64 * PW_PITCH;
#pragma unroll
        for (int ks = 0; ks < 2; ++ks) {
            uint32_t afr[2][4], bfr[2][4];
#pragma unroll
            for (int mf = 0; mf < 2; ++mf) {
                uint32_t addr = sA + (warpM * 32 + mf * 16 + (lane & 15)) * PW_PITCH
                                   + (ks * 2 + (lane >> 4)) * 16;
                ldsm4(afr[mf], addr);
            }
#pragma unroll
            for (int nq = 0; nq < 2; ++nq) {
                uint32_t addr = sB + (warpN * 32 + nq * 16 + (lane & 7) + ((lane >> 4) & 1) * 8) * PW_PITCH
                                   + (ks * 2 + ((lane >> 3) & 1)) * 16;
                ldsm4(bfr[nq], addr);
            }
#pragma unroll
            for (int mf = 0; mf < 2; ++mf)
#pragma unroll
                for (int nq = 0; nq < 2; ++nq) {
                    mma16816(acc[mf][nq * 2],     afr[mf], bfr[nq][0], bfr[nq][1]);
                    mma16816(acc[mf][nq * 2 + 1], afr[mf], bfr[nq][2], bfr[nq][3]);
                }
        }
    }
#pragma unroll
    for (int mf = 0; mf < 2; ++mf)
#pragma unroll
        for (int hr = 0; hr < 2; ++hr) {
            int row = m0 + warpM * 32 + mf * 16 + hr * 8 + (lane >> 2);
#pragma unroll
            for (int nf = 0; nf < 4; ++nf) {
                int col = n0 + warpN * 32 + nf * 8 + (lane & 3) * 2;
                __half2 h = __floats2half2_rn(acc[mf][nf][2 * hr], acc[mf][nf][2 * hr + 1]);
                *(__half2*)&g_PW[(size_t)row * HID_ + col] = h;
            }
        }
}

// ---------------- main GEMM: persistent X, B via direct LDG, barrier-free mainloop ----
// smem: X only: 128*768 = 98304
#define SMEM_BYTES  98304

#define KT_   12                 // k32 stages per n-tile
#define IT_   144                // 12 n-tiles * 12

__global__ void __launch_bounds__(256, 2)
k_gemm(const float* __restrict__ b1, const float* __restrict__ W2,
       const float* __restrict__ b2, float* __restrict__ out)
{
    extern __shared__ char smem[];
    const int tid   = threadIdx.x;
    const int lane  = tid & 31;
    const int wid   = tid >> 5;
    const int warpM = wid >> 1;          // 0..3
    const int warpN = wid & 1;           // 0..1
    const int m0    = blockIdx.x * 128;
    const uint32_t xbase = smem_u32(smem);

    // ---- kick off persistent X load, overlap with gather ----
#pragma unroll
    for (int i = 0; i < 24; ++i) {
        int idx = tid + i * 256;
        int r = idx / 48, c = idx % 48;
        CPASYNC16(xbase + swzX(r, c),
                  (const void*)&g_X[(size_t)(m0 + r) * KD_ + c * 8]);
    }
    CPCOMMIT();

    // ---- one-time mean gather for this CTA's 128 rows -> g_MX slice ----
#pragma unroll 1
    for (int j = 0; j < 16; ++j) {
        int r  = wid * 16 + j;
        int m  = m0 + r;
        int bb = m / N_;
        int nn = m - bb * N_;
        int ec = g_cnt[nn];
        if (ec > SLOTS_) ec = SLOTS_;
        float inv = 1.0f / fmaxf((float)ec, 1.0f);
        float fs[24];
#pragma unroll
        for (int o = 0; o < 24; ++o) fs[o] = 0.0f;
        for (int e = 0; e < ec; ++e) {
            int pp = g_eslot[nn * SLOTS_ + e];
            const uint4* pr = (const uint4*)&g_PW[((size_t)(bb * P_ + pp)) * HID_];
#pragma unroll
            for (int u = 0; u < 3; ++u) {
                union { uint4 v; __half2 h[4]; } cv;
                cv.v = pr[lane + 32 * u];
#pragma unroll
                for (int o = 0; o < 4; ++o) {
                    float2 f = __half22float2(cv.h[o]);
                    fs[u * 8 + o * 2]     += f.x;
                    fs[u * 8 + o * 2 + 1] += f.y;
                }
            }
        }
        uint4* dst = (uint4*)&g_MX[(size_t)m * HID_];
#pragma unroll
        for (int u = 0; u < 3; ++u) {
            union { uint4 v; __half2 h[4]; } ov;
#pragma unroll
            for (int o = 0; o < 4; ++o)
                ov.h[o] = __floats2half2_rn(fs[u * 8 + o * 2] * inv, fs[u * 8 + o * 2 + 1] * inv);
            dst[lane + 32 * u] = ov.v;
        }
    }
    // X resident before any ldsm; single barrier of the whole mainloop phase
    CPWAIT0();
    __syncthreads();

    // per-thread B base: W1t[n = warpN*32 + lane/4][k = (lane&3)*2]
    const __half* bbase = g_W1t + (size_t)(warpN * 32 + (lane >> 2)) * KD_ + (lane & 3) * 2;

    // persistent GEMM2 MMA accumulators: out tile m32 x n16 per warp
    float pers[2][2][4];
#pragma unroll
    for (int mf = 0; mf < 2; ++mf)
#pragma unroll
        for (int nfr = 0; nfr < 2; ++nfr)
#pragma unroll
            for (int q = 0; q < 4; ++q) pers[mf][nfr][q] = 0.0f;

    float acc[2][4][4];
#pragma unroll
    for (int mf = 0; mf < 2; ++mf)
#pragma unroll
        for (int nf = 0; nf < 4; ++nf)
#pragma unroll
            for (int q = 0; q < 4; ++q) acc[mf][nf][q] = 0.0f;

    // ---- barrier-free mainloop: 144 k32 stages, B fragments via LDG ----
    int kk = 0, nt = 0;
#pragma unroll 1
    for (int s = 0; s < IT_; ++s) {
        // B fragments for this stage: 4 n8 blocks x 2 k16 halves x {b0,b1}
        const __half* bs = bbase + (size_t)nt * 64 * KD_ + kk * 32;
        uint32_t bq[2][4][2];
#pragma unroll
        for (int ks = 0; ks < 2; ++ks)
#pragma unroll
            for (int blk = 0; blk < 4; ++blk) {
                const __half* p = bs + (size_t)blk * 8 * KD_ + ks * 16;
                bq[ks][blk][0] = __ldg((const uint32_t*)p);
                bq[ks][blk][1] = __ldg((const uint32_t*)(p + 8));
            }

#pragma unroll
        for (int ks = 0; ks < 2; ++ks) {
            uint32_t afr[2][4];
#pragma unroll
            for (int mf = 0; mf < 2; ++mf) {
                int rA = warpM * 32 + mf * 16 + (lane & 15);
                int ch = kk * 4 + ks * 2 + (lane >> 4);
                ldsm4(afr[mf], xbase + swzX(rA, ch));
            }
#pragma unroll
            for (int mf = 0; mf < 2; ++mf)
#pragma unroll
                for (int nq = 0; nq < 2; ++nq) {
                    mma16816(acc[mf][nq * 2],     afr[mf], bq[ks][nq * 2][0],     bq[ks][nq * 2][1]);
                    mma16816(acc[mf][nq * 2 + 1], afr[mf], bq[ks][nq * 2 + 1][0], bq[ks][nq * 2 + 1][1]);
                }
        }

        // ---- n-tile boundary: relu/bias/mean then GEMM2 on tensor cores ----
        if (++kk == KT_) {
            kk = 0;
            const int n0 = nt * 64;

            // W2 B-fragments: this warp's 32 hidden cols = 2 k16 chunks of GEMM2
            uint32_t bw2[2][2][2];
            {
                const int kb  = n0 + warpN * 32 + (lane & 3) * 2;
                const int nc0 = lane >> 2;
#pragma unroll
                for (int ch = 0; ch < 2; ++ch) {
                    int k0 = kb + ch * 16;
#pragma unroll
                    for (int nfr = 0; nfr < 2; ++nfr) {
                        int nc = nc0 + nfr * 8;
                        if (nc < 12) {
                            float w0  = __ldg(&W2[(size_t)(k0    ) * 12 + nc]);
                            float w1  = __ldg(&W2[(size_t)(k0 + 1) * 12 + nc]);
                            float w2v = __ldg(&W2[(size_t)(k0 + 8) * 12 + nc]);
                            float w3  = __ldg(&W2[(size_t)(k0 + 9) * 12 + nc]);
                            bw2[ch][nfr][0] = packh2(w0, w1);
                            bw2[ch][nfr][1] = packh2(w2v, w3);
                        } else {
                            bw2[ch][nfr][0] = 0u;
                            bw2[ch][nfr][1] = 0u;
                        }
                    }
                }
            }

#pragma unroll
            for (int mf = 0; mf < 2; ++mf) {
                const int rlo = warpM * 32 + mf * 16 + (lane >> 2);
                const size_t mlo = (size_t)(m0 + rlo) * HID_;
                const size_t mhi = mlo + 8 * HID_;
                uint32_t afr2[2][4];
#pragma unroll
                for (int nf = 0; nf < 4; ++nf) {
                    int col0 = n0 + warpN * 32 + nf * 8 + (lane & 3) * 2;
                    float2 lo2 = __half22float2(*(const __half2*)&g_MX[mlo + col0]);
                    float2 hi2 = __half22float2(*(const __half2*)&g_MX[mhi + col0]);
                    float b1a = __ldg(&b1[col0]);
                    float b1b = __ldg(&b1[col0 + 1]);
                    float v0 = fmaxf(acc[mf][nf][0] + lo2.x + b1a, 0.0f);
                    float v1 = fmaxf(acc[mf][nf][1] + lo2.y + b1b, 0.0f);
                    float v2 = fmaxf(acc[mf][nf][2] + hi2.x + b1a, 0.0f);
                    float v3 = fmaxf(acc[mf][nf][3] + hi2.y + b1b, 0.0f);
                    int ch = nf >> 1, hp = nf & 1;
                    afr2[ch][hp * 2 + 0] = packh2(v0, v1);
                    afr2[ch][hp * 2 + 1] = packh2(v2, v3);
                }
#pragma unroll
                for (int ch = 0; ch < 2; ++ch)
#pragma unroll
                    for (int nfr = 0; nfr < 2; ++nfr)
                        mma16816(pers[mf][nfr], afr2[ch], bw2[ch][nfr][0], bw2[ch][nfr][1]);
            }
#pragma unroll
            for (int mf = 0; mf < 2; ++mf)
#pragma unroll
                for (int nf = 0; nf < 4; ++nf)
#pragma unroll
                    for (int q = 0; q < 4; ++q) acc[mf][nf][q] = 0.0f;
            ++nt;
        }
    }

    // ---- cross-warpN reduce (reuse X smem area), then global write ----
    float* red = (float*)smem;   // 128 rows x 16 cols = 8192 B
    __syncthreads();
    if (warpN == 1) {
#pragma unroll
        for (int mf = 0; mf < 2; ++mf) {
            int rlo = warpM * 32 + mf * 16 + (lane >> 2);
#pragma unroll
            for (int nfr = 0; nfr < 2; ++nfr) {
                int col = (lane & 3) * 2 + nfr * 8;
                red[rlo * 16 + col]           = pers[mf][nfr][0];
                red[rlo * 16 + col + 1]       = pers[mf][nfr][1];
                red[(rlo + 8) * 16 + col]     = pers[mf][nfr][2];
                red[(rlo + 8) * 16 + col + 1] = pers[mf][nfr][3];
            }
        }
    }
    __syncthreads();
    if (warpN == 0) {
#pragma unroll
        for (int mf = 0; mf < 2; ++mf) {
            int rlo = warpM * 32 + mf * 16 + (lane >> 2);
            size_t glo = (size_t)(m0 + rlo) * 12;
            size_t ghi = glo + 8 * 12;
#pragma unroll
            for (int nfr = 0; nfr < 2; ++nfr) {
                int col = (lane & 3) * 2 + nfr * 8;
                if (col < 12) {
                    out[glo + col]     = pers[mf][nfr][0] + red[rlo * 16 + col]           + b2[col];
                    out[glo + col + 1] = pers[mf][nfr][1] + red[rlo * 16 + col + 1]       + b2[col + 1];
                    out[ghi + col]     = pers[mf][nfr][2] + red[(rlo + 8) * 16 + col]     + b2[col];
                    out[ghi + col + 1] = pers[mf][nfr][3] + red[(rlo + 8) * 16 + col + 1] + b2[col + 1];
                }
            }
        }
    }
}

// ---------------- launch ----------------
extern "C" void kernel_launch(void* const* d_in, const int* in_sizes, int n_in,
                              void* d_out, int out_size)
{
    const float* patch  = (const float*)d_in[0];
    const float* nodes  = (const float*)d_in[1];
    const int*   batch  = (const int*)d_in[2];
    const int*   mapper = (const int*)d_in[3];
    const float* W1     = (const float*)d_in[4];
    const float* b1     = (const float*)d_in[5];
    const float* W2     = (const float*)d_in[6];
    const float* b2     = (const float*)d_in[7];
    float*       out    = (float*)d_out;

    k_conv<<<(CONV_WORK + 255) / 256, 256>>>(W1, nodes, patch);                     // 0
    dim3 pwgrid(BP_ / 64, HID_ / 128);
    k_pw<<<pwgrid, 256>>>();                                                        // 1
    k_scatter<<<(E_ + 255) / 256, 256>>>(mapper, batch);                            // 2
    cudaFuncSetAttribute(k_gemm, cudaFuncAttributeMaxDynamicSharedMemorySize, SMEM_BYTES);
    k_gemm<<<M_ / 128, 256, SMEM_BYTES>>>(b1, W2, b2, out);                         // 3
}

// round 17
// speedup vs baseline: 1.9336x; 1.9336x over previous
#include <cuda_runtime.h>
#include <cuda_fp16.h>
#include <cstdint>
#include <cstddef>

// ---------------- problem constants ----------------
#define B_   8
#define T_   12
#define P_   1000
#define N_   20000
#define E_   60000
#define FP_  32
#define FN_  32
#define H_   12
#define KD_  384                 // GEMM1 K after PW split
#define HID_ 768
#define M_   (B_ * N_)           // 160000 rows
#define BP_  (B_ * P_)           // 8000 distinct patch rows
#define SLOTS_ 32                // padded fan-in per node (max observed ~15)

// ---------------- device scratch ----------------
__device__ __half g_X[(size_t)M_ * KD_];
__device__ __half g_W1t[HID_ * KD_];        // W1 top half transposed
__device__ __half g_W1bt[HID_ * KD_];       // W1 bottom half transposed
__device__ __half g_Pf[BP_ * KD_];
__device__ __half g_PW[(size_t)BP_ * HID_];
__device__ __half g_MX[(size_t)M_ * HID_];  // per-row mean of PW rows
__device__ int    g_cnt[N_];                // per-node edge count (zeroed by k_conv)
__device__ int    g_eslot[N_ * SLOTS_];     // padded per-node patch indices

// ---------------- fused conversions + cnt zeroing ----------------
#define W1T_WORK (HID_ * HID_)
#define NX_WORK  (B_ * T_ * N_ * 4)
#define PF_WORK  (B_ * T_ * P_ * 4)
#define CONV_WORK (W1T_WORK + NX_WORK + PF_WORK + N_)
__global__ void k_conv(const float* __restrict__ W1, const float* __restrict__ nodes_x,
                       const float* __restrict__ patch) {
    int i = blockIdx.x * blockDim.x + threadIdx.x;
    if (i < W1T_WORK) {
        int k = i / HID_, h = i % HID_;
        __half v = __float2half_rn(W1[i]);
        if (k < KD_) g_W1t[h * KD_ + k] = v;
        else         g_W1bt[h * KD_ + (k - KD_)] = v;
    } else if (i < W1T_WORK + NX_WORK) {
        int j = i - W1T_WORK;
        int q  = j & 3;
        int n  = (j >> 2) % N_;
        int bt = (j >> 2) / N_;
        int b = bt / T_, t = bt % T_;
        const float4* src = (const float4*)(nodes_x + ((size_t)bt * N_ + n) * FN_ + q * 8);
        float4 a = src[0], c = src[1];
        union { __half2 h[4]; uint4 u; } cv;
        cv.h[0] = __floats2half2_rn(a.x, a.y);
        cv.h[1] = __floats2half2_rn(a.z, a.w);
        cv.h[2] = __floats2half2_rn(c.x, c.y);
        cv.h[3] = __floats2half2_rn(c.z, c.w);
        *(uint4*)&g_X[((size_t)(b * N_ + n)) * KD_ + t * FN_ + q * 8] = cv.u;
    } else if (i < W1T_WORK + NX_WORK + PF_WORK) {
        int j = i - W1T_WORK - NX_WORK;
        int q  = j & 3;
        int p  = (j >> 2) % P_;
        int bt = (j >> 2) / P_;
        int b = bt / T_, t = bt % T_;
        const float4* src = (const float4*)(patch + ((size_t)bt * P_ + p) * FP_ + q * 8);
        float4 a = src[0], c = src[1];
        union { __half2 h[4]; uint4 u; } cv;
        cv.h[0] = __floats2half2_rn(a.x, a.y);
        cv.h[1] = __floats2half2_rn(a.z, a.w);
        cv.h[2] = __floats2half2_rn(c.x, c.y);
        cv.h[3] = __floats2half2_rn(c.z, c.w);
        *(uint4*)&g_Pf[((size_t)(b * P_ + p)) * KD_ + t * FP_ + q * 8] = cv.u;
    } else if (i < CONV_WORK) {
        g_cnt[i - (W1T_WORK + NX_WORK + PF_WORK)] = 0;
    }
}

// ---------------- edge scatter into padded slots ----------------
__global__ void k_scatter(const int* __restrict__ mapper, const int* __restrict__ batch) {
    int e = blockIdx.x * blockDim.x + threadIdx.x;
    if (e < E_) {
        int n = mapper[e];
        int idx = atomicAdd(&g_cnt[n], 1);
        if (idx < SLOTS_) g_eslot[n * SLOTS_ + idx] = batch[e];
    }
}

// ---------------- mma helpers ----------------
__device__ __forceinline__ uint32_t smem_u32(const void* p) {
    uint32_t a;
    asm volatile("{ .reg .u64 t; cvta.to.shared.u64 t, %1; cvt.u32.u64 %0, t; }"
                 : "=r"(a) : "l"(p));
    return a;
}
__device__ __forceinline__ void ldsm4(uint32_t* r, uint32_t addr) {
    asm volatile("ldmatrix.sync.aligned.m8n8.x4.shared.b16 {%0,%1,%2,%3}, [%4];"
                 : "=r"(r[0]), "=r"(r[1]), "=r"(r[2]), "=r"(r[3]) : "r"(addr));
}
__device__ __forceinline__ void mma16816(float* c, const uint32_t* a,
                                         uint32_t b0, uint32_t b1) {
    asm volatile("mma.sync.aligned.m16n8k16.row.col.f32.f16.f16.f32 "
                 "{%0,%1,%2,%3}, {%4,%5,%6,%7}, {%8,%9}, {%0,%1,%2,%3};"
                 : "+f"(c[0]), "+f"(c[1]), "+f"(c[2]), "+f"(c[3])
                 : "r"(a[0]), "r"(a[1]), "r"(a[2]), "r"(a[3]), "r"(b0), "r"(b1));
}
__device__ __forceinline__ uint32_t packh2(float a, float b) {
    __half2 h = __floats2half2_rn(a, b);
    return *(uint32_t*)&h;
}
#define CPASYNC16(dst, src) \
    asm volatile("cp.async.cg.shared.global [%0], [%1], 16;" :: "r"(dst), "l"(src))
#define CPCOMMIT() asm volatile("cp.async.commit_group;" ::: "memory")
#define CPWAIT1()  asm volatile("cp.async.wait_group 1;" ::: "memory")
#define CPWAIT0()  asm volatile("cp.async.wait_group 0;" ::: "memory")

// persistent X tile: 768B pitch (48 x 16B chunks), XOR-swizzled by row
__device__ __forceinline__ uint32_t swzX(int r, int c) {
    return (uint32_t)(r * 768 + ((c ^ (r & 7)) << 4));
}
// B k64 stage tile: 128B pitch (8 x 16B chunks), XOR-swizzled by row
__device__ __forceinline__ uint32_t swzB(int r, int c) {
    return (uint32_t)(r * 128 + ((c ^ (r & 7)) << 4));
}

// ---------------- k_pw: PW[8000,768] = Pf @ W1bt^T ----------------
#define PW_PITCH 80
#define PW_STAGE (192 * PW_PITCH)
__global__ void __launch_bounds__(256, 1)
k_pw()
{
    __shared__ char smem[3 * PW_STAGE];
    const int tid   = threadIdx.x;
    const int lane  = tid & 31;
    const int wid   = tid >> 5;
    const int warpM = wid >> 2;
    const int warpN = wid & 3;
    const int m0    = blockIdx.x * 64;
    const int n0    = blockIdx.y * 128;
    const uint32_t tile_base = smem_u32(smem);
    const int r0 = tid >> 2;
    const int c0 = tid & 3;

    float acc[2][4][4];
#pragma unroll
    for (int mf = 0; mf < 2; ++mf)
#pragma unroll
        for (int nf = 0; nf < 4; ++nf)
#pragma unroll
            for (int q = 0; q < 4; ++q) acc[mf][nf][q] = 0.0f;

#pragma unroll
    for (int s = 0; s < 2; ++s) {
        const int k0 = s * 32;
        uint32_t sA = tile_base + s * PW_STAGE;
        uint32_t sB = sA + 64 * PW_PITCH;
        CPASYNC16(sA + r0 * PW_PITCH + c0 * 16,
                  (const void*)&g_Pf[(size_t)(m0 + r0) * KD_ + k0 + c0 * 8]);
        CPASYNC16(sB + r0 * PW_PITCH + c0 * 16,
                  (const void*)&g_W1bt[(size_t)(n0 + r0) * KD_ + k0 + c0 * 8]);
        CPASYNC16(sB + (r0 + 64) * PW_PITCH + c0 * 16,
                  (const void*)&g_W1bt[(size_t)(n0 + r0 + 64) * KD_ + k0 + c0 * 8]);
        CPCOMMIT();
    }

#pragma unroll 1
    for (int kt = 0; kt < 12; ++kt) {
        if (kt < 11) { CPWAIT1(); } else { CPWAIT0(); }
        __syncthreads();
        if (kt + 2 < 12) {
            const int k0 = (kt + 2) * 32;
            const int st = (kt + 2) % 3;
            uint32_t sA = tile_base + st * PW_STAGE;
            uint32_t sB = sA + 64 * PW_PITCH;
            CPASYNC16(sA + r0 * PW_PITCH + c0 * 16,
                      (const void*)&g_Pf[(size_t)(m0 + r0) * KD_ + k0 + c0 * 8]);
            CPASYNC16(sB + r0 * PW_PITCH + c0 * 16,
                      (const void*)&g_W1bt[(size_t)(n0 + r0) * KD_ + k0 + c0 * 8]);
            CPASYNC16(sB + (r0 + 64) * PW_PITCH + c0 * 16,
                      (const void*)&g_W1bt[(size_t)(n0 + r0 + 64) * KD_ + k0 + c0 * 8]);
            CPCOMMIT();
        }
        const int st = kt % 3;
        uint32_t sA = tile_base + st * PW_STAGE;
        uint32_t sB = sA + 64 * PW_PITCH;
#pragma unroll
        for (int ks = 0; ks < 2; ++ks) {
            uint32_t afr[2][4], bfr[2][4];
#pragma unroll
            for (int mf = 0; mf < 2; ++mf) {
                uint32_t addr = sA + (warpM * 32 + mf * 16 + (lane & 15)) * PW_PITCH
                                   + (ks * 2 + (lane >> 4)) * 16;
                ldsm4(afr[mf], addr);
            }
#pragma unroll
            for (int nq = 0; nq < 2; ++nq) {
                uint32_t addr = sB + (warpN * 32 + nq * 16 + (lane & 7) + ((lane >> 4) & 1) * 8) * PW_PITCH
                                   + (ks * 2 + ((lane >> 3) & 1)) * 16;
                ldsm4(bfr[nq], addr);
            }
#pragma unroll
            for (int mf = 0; mf < 2; ++mf)
#pragma unroll
                for (int nq = 0; nq < 2; ++nq) {
                    mma16816(acc[mf][nq * 2],     afr[mf], bfr[nq][0], bfr[nq][1]);
                    mma16816(acc[mf][nq * 2 + 1], afr[mf], bfr[nq][2], bfr[nq][3]);
                }
        }
    }
#pragma unroll
    for (int mf = 0; mf < 2; ++mf)
#pragma unroll
        for (int hr = 0; hr < 2; ++hr) {
            int row = m0 + warpM * 32 + mf * 16 + hr * 8 + (lane >> 2);
#pragma unroll
            for (int nf = 0; nf < 4; ++nf) {
                int col = n0 + warpN * 32 + nf * 8 + (lane & 3) * 2;
                __half2 h = __floats2half2_rn(acc[mf][nf][2 * hr], acc[mf][nf][2 * hr + 1]);
                *(__half2*)&g_PW[(size_t)row * HID_ + col] = h;
            }
        }
}

// ---------------- main GEMM: persistent X, double-buffered K64 B stages ----------------
// smem: X @0 (128*768 = 98304) | B @98304 (2 * 64*128 = 16384) => 114688
#define SM_XB       98304
#define BSTAGE_     8192
#define SMEM_BYTES  114688

#define KP_   6                  // k64 stages per n-tile (384/64)
#define IT_   72                 // 12 n-tiles * 6

__global__ void __launch_bounds__(256, 2)
k_gemm(const float* __restrict__ b1, const float* __restrict__ W2,
       const float* __restrict__ b2, float* __restrict__ out)
{
    extern __shared__ char smem[];
    const int tid   = threadIdx.x;
    const int lane  = tid & 31;
    const int wid   = tid >> 5;
    const int warpM = wid >> 1;          // 0..3
    const int warpN = wid & 1;           // 0..1
    const int m0    = blockIdx.x * 128;
    const uint32_t xbase = smem_u32(smem);
    const uint32_t bbase = xbase + SM_XB;

    // ---- kick off persistent X load, overlap with gather ----
#pragma unroll
    for (int i = 0; i < 24; ++i) {
        int idx = tid + i * 256;
        int r = idx / 48, c = idx % 48;
        CPASYNC16(xbase + swzX(r, c),
                  (const void*)&g_X[(size_t)(m0 + r) * KD_ + c * 8]);
    }
    CPCOMMIT();

    // ---- one-time mean gather for this CTA's 128 rows -> g_MX slice ----
#pragma unroll 1
    for (int j = 0; j < 16; ++j) {
        int r  = wid * 16 + j;
        int m  = m0 + r;
        int bb = m / N_;
        int nn = m - bb * N_;
        int ec = g_cnt[nn];
        if (ec > SLOTS_) ec = SLOTS_;
        float inv = 1.0f / fmaxf((float)ec, 1.0f);
        float fs[24];
#pragma unroll
        for (int o = 0; o < 24; ++o) fs[o] = 0.0f;
        for (int e = 0; e < ec; ++e) {
            int pp = g_eslot[nn * SLOTS_ + e];
            const uint4* pr = (const uint4*)&g_PW[((size_t)(bb * P_ + pp)) * HID_];
#pragma unroll
            for (int u = 0; u < 3; ++u) {
                union { uint4 v; __half2 h[4]; } cv;
                cv.v = pr[lane + 32 * u];
#pragma unroll
                for (int o = 0; o < 4; ++o) {
                    float2 f = __half22float2(cv.h[o]);
                    fs[u * 8 + o * 2]     += f.x;
                    fs[u * 8 + o * 2 + 1] += f.y;
                }
            }
        }
        uint4* dst = (uint4*)&g_MX[(size_t)m * HID_];
#pragma unroll
        for (int u = 0; u < 3; ++u) {
            union { uint4 v; __half2 h[4]; } ov;
#pragma unroll
            for (int o = 0; o < 4; ++o)
                ov.h[o] = __floats2half2_rn(fs[u * 8 + o * 2] * inv, fs[u * 8 + o * 2 + 1] * inv);
            dst[lane + 32 * u] = ov.v;
        }
    }
    CPWAIT0();        // X resident
    __syncthreads();

    // B stage load coords: 512 16B chunks, 2 per thread
    const int rB = tid >> 2;             // 0..63 (row within 64-row tile)
    const int cB0 = (tid & 3) * 2;       // chunks cB0, cB0+1

    // ---- B prologue: stage 0 (nt=0, k0=0) ----
    CPASYNC16(bbase + swzB(rB, cB0),
              (const void*)&g_W1t[(size_t)rB * KD_ + cB0 * 8]);
    CPASYNC16(bbase + swzB(rB, cB0 + 1),
              (const void*)&g_W1t[(size_t)rB * KD_ + cB0 * 8 + 8]);
    CPCOMMIT();

    // persistent GEMM2 MMA accumulators: out tile m32 x n16 per warp
    float pers[2][2][4];
#pragma unroll
    for (int mf = 0; mf < 2; ++mf)
#pragma unroll
        for (int nfr = 0; nfr < 2; ++nfr)
#pragma unroll
            for (int q = 0; q < 4; ++q) pers[mf][nfr][q] = 0.0f;

    float acc[2][4][4];
#pragma unroll
    for (int mf = 0; mf < 2; ++mf)
#pragma unroll
        for (int nf = 0; nf < 4; ++nf)
#pragma unroll
            for (int q = 0; q < 4; ++q) acc[mf][nf][q] = 0.0f;

    // ---- mainloop: 72 k64 stages, double-buffered, one barrier per stage ----
    int kp = 0, nt = 0;
#pragma unroll 1
    for (int s = 0; s < IT_; ++s) {
        CPWAIT0();        // stage s resident
        __syncthreads();  // all warps done with buffer (s+1)&1 (stage s-1)

        // prefetch stage s+1 into the other buffer; overlaps compute + epilogue
        if (s + 1 < IT_) {
            const int sg   = s + 1;
            const int pkp  = (kp + 1 == KP_) ? 0 : kp + 1;
            const int pnt  = (kp + 1 == KP_) ? nt + 1 : nt;
            const size_t gb = (size_t)(pnt * 64 + rB) * KD_ + pkp * 64 + cB0 * 8;
            uint32_t dstb = bbase + ((sg & 1) * BSTAGE_);
            CPASYNC16(dstb + swzB(rB, cB0),     (const void*)&g_W1t[gb]);
            CPASYNC16(dstb + swzB(rB, cB0 + 1), (const void*)&g_W1t[gb + 8]);
            CPCOMMIT();
        }

        // ---- compute stage s: 4 k16 steps ----
        {
            uint32_t sB = bbase + (s & 1) * BSTAGE_;
#pragma unroll
            for (int ks = 0; ks < 4; ++ks) {
                uint32_t afr[2][4], bfr[2][4];
#pragma unroll
                for (int mf = 0; mf < 2; ++mf) {
                    int rA = warpM * 32 + mf * 16 + (lane & 15);
                    int ch = kp * 8 + ks * 2 + (lane >> 4);
                    ldsm4(afr[mf], xbase + swzX(rA, ch));
                }
#pragma unroll
                for (int nq = 0; nq < 2; ++nq) {
                    int rb = warpN * 32 + nq * 16 + (lane & 7) + ((lane >> 4) & 1) * 8;
                    int ch = ks * 2 + ((lane >> 3) & 1);
                    ldsm4(bfr[nq], sB + swzB(rb, ch));
                }
#pragma unroll
                for (int mf = 0; mf < 2; ++mf)
#pragma unroll
                    for (int nq = 0; nq < 2; ++nq) {
                        mma16816(acc[mf][nq * 2],     afr[mf], bfr[nq][0], bfr[nq][1]);
                        mma16816(acc[mf][nq * 2 + 1], afr[mf], bfr[nq][2], bfr[nq][3]);
                    }
            }
        }

        // ---- n-tile boundary: relu/bias/mean then GEMM2 on tensor cores ----
        if (++kp == KP_) {
            kp = 0;
            const int n0 = nt * 64;

            uint32_t bw2[2][2][2];
            {
                const int kb  = n0 + warpN * 32 + (lane & 3) * 2;
                const int nc0 = lane >> 2;
#pragma unroll
                for (int ch = 0; ch < 2; ++ch) {
                    int k0 = kb + ch * 16;
#pragma unroll
                    for (int nfr = 0; nfr < 2; ++nfr) {
                        int nc = nc0 + nfr * 8;
                        if (nc < 12) {
                            float w0  = __ldg(&W2[(size_t)(k0    ) * 12 + nc]);
                            float w1  = __ldg(&W2[(size_t)(k0 + 1) * 12 + nc]);
                            float w2v = __ldg(&W2[(size_t)(k0 + 8) * 12 + nc]);
                            float w3  = __ldg(&W2[(size_t)(k0 + 9) * 12 + nc]);
                            bw2[ch][nfr][0] = packh2(w0, w1);
                            bw2[ch][nfr][1] = packh2(w2v, w3);
                        } else {
                            bw2[ch][nfr][0] = 0u;
                            bw2[ch][nfr][1] = 0u;
                        }
                    }
                }
            }

#pragma unroll
            for (int mf = 0; mf < 2; ++mf) {
                const int rlo = warpM * 32 + mf * 16 + (lane >> 2);
                const size_t mlo = (size_t)(m0 + rlo) * HID_;
                const size_t mhi = mlo + 8 * HID_;
                uint32_t afr2[2][4];
#pragma unroll
                for (int nf = 0; nf < 4; ++nf) {
                    int col0 = n0 + warpN * 32 + nf * 8 + (lane & 3) * 2;
                    float2 lo2 = __half22float2(*(const __half2*)&g_MX[mlo + col0]);
                    float2 hi2 = __half22float2(*(const __half2*)&g_MX[mhi + col0]);
                    float b1a = __ldg(&b1[col0]);
                    float b1b = __ldg(&b1[col0 + 1]);
                    float v0 = fmaxf(acc[mf][nf][0] + lo2.x + b1a, 0.0f);
                    float v1 = fmaxf(acc[mf][nf][1] + lo2.y + b1b, 0.0f);
                    float v2 = fmaxf(acc[mf][nf][2] + hi2.x + b1a, 0.0f);
                    float v3 = fmaxf(acc[mf][nf][3] + hi2.y + b1b, 0.0f);
                    int ch = nf >> 1, hp = nf & 1;
                    afr2[ch][hp * 2 + 0] = packh2(v0, v1);
                    afr2[ch][hp * 2 + 1] = packh2(v2, v3);
                }
#pragma unroll
                for (int ch = 0; ch < 2; ++ch)
#pragma unroll
                    for (int nfr = 0; nfr < 2; ++nfr)
                        mma16816(pers[mf][nfr], afr2[ch], bw2[ch][nfr][0], bw2[ch][nfr][1]);
            }
#pragma unroll
            for (int mf = 0; mf < 2; ++mf)
#pragma unroll
                for (int nf = 0; nf < 4; ++nf)
#pragma unroll
                    for (int q = 0; q < 4; ++q) acc[mf][nf][q] = 0.0f;
            ++nt;
        }
    }

    // ---- cross-warpN reduce (reuse X smem area), then global write ----
    float* red = (float*)smem;   // 128 rows x 16 cols = 8192 B
    __syncthreads();
    if (warpN == 1) {
#pragma unroll
        for (int mf = 0; mf < 2; ++mf) {
            int rlo = warpM * 32 + mf * 16 + (lane >> 2);
#pragma unroll
            for (int nfr = 0; nfr < 2; ++nfr) {
                int col = (lane & 3) * 2 + nfr * 8;
                red[rlo * 16 + col]           = pers[mf][nfr][0];
                red[rlo * 16 + col + 1]       = pers[mf][nfr][1];
                red[(rlo + 8) * 16 + col]     = pers[mf][nfr][2];
                red[(rlo + 8) * 16 + col + 1] = pers[mf][nfr][3];
            }
        }
    }
    __syncthreads();
    if (warpN == 0) {
#pragma unroll
        for (int mf = 0; mf < 2; ++mf) {
            int rlo = warpM * 32 + mf * 16 + (lane >> 2);
            size_t glo = (size_t)(m0 + rlo) * 12;
            size_t ghi = glo + 8 * 12;
#pragma unroll
            for (int nfr = 0; nfr < 2; ++nfr) {
                int col = (lane & 3) * 2 + nfr * 8;
                if (col < 12) {
                    out[glo + col]     = pers[mf][nfr][0] + red[rlo * 16 + col]           + b2[col];
                    out[glo + col + 1] = pers[mf][nfr][1] + red[rlo * 16 + col + 1]       + b2[col + 1];
                    out[ghi + col]     = pers[mf][nfr][2] + red[(rlo + 8) * 16 + col]     + b2[col];
                    out[ghi + col + 1] = pers[mf][nfr][3] + red[(rlo + 8) * 16 + col + 1] + b2[col + 1];
                }
            }
        }
    }
}

// ---------------- launch ----------------
extern "C" void kernel_launch(void* const* d_in, const int* in_sizes, int n_in,
                              void* d_out, int out_size)
{
    const float* patch  = (const float*)d_in[0];
    const float* nodes  = (const float*)d_in[1];
    const int*   batch  = (const int*)d_in[2];
    const int*   mapper = (const int*)d_in[3];
    const float* W1     = (const float*)d_in[4];
    const float* b1     = (const float*)d_in[5];
    const float* W2     = (const float*)d_in[6];
    const float* b2     = (const float*)d_in[7];
    float*       out    = (float*)d_out;

    k_conv<<<(CONV_WORK + 255) / 256, 256>>>(W1, nodes, patch);                     // 0
    dim3 pwgrid(BP_ / 64, HID_ / 128);
    k_pw<<<pwgrid, 256>>>();                                                        // 1
    k_scatter<<<(E_ + 255) / 256, 256>>>(mapper, batch);                            // 2
    cudaFuncSetAttribute(k_gemm, cudaFuncAttributeMaxDynamicSharedMemorySize, SMEM_BYTES);
    k_gemm<<<M_ / 128, 256, SMEM_BYTES>>>(b1, W2, b2, out);                         // 3
}